// round 2
// baseline (speedup 1.0000x reference)
#include <cuda_runtime.h>
#include <cuda_bf16.h>
#include <cstdint>

// ---------------------------------------------------------------------------
// BlockDiagonalGRU via mma.sync tf32 (sm_100 base target compatible).
//   x:(1024,4096) h:(1024,4096) W_ih:(8,1536,512) W_hh:(8,1536,512)
//   b_ih:(8,1536) b_hh:(8,1536) -> out:(1024,4096), all fp32
//
// Grid: 512 CTAs = nb(8) x ctile(8, 64 cols) x mtile(8, 128 rows), m fastest.
// CTA tile: 128 x 64 per gate. 8 warps as 4(m) x 2(n), warp tile 32 x 32.
// Register accumulators: R (=i_r+h_r fused), Z (fused), IN, HN  -> 128 f32/thread.
// K pipeline: 32-wide k-chunks, 2-stage SMEM double buffer, manual LDG prefetch,
// fp32 -> tf32 (cvt.rna) applied on the STS side.
// ---------------------------------------------------------------------------

namespace {

constexpr int HID = 4096;
constexpr int BS  = 512;
constexpr int G3  = 1536;
constexpr int TK  = 32;

constexpr int A_ROWS = 128;
constexpr int B_ROWS = 192;        // 3 gates x 64 cols
constexpr int LDS_STRIDE = 36;     // 32 + 4 pad: conflict-free frag loads
constexpr int A_F = A_ROWS * LDS_STRIDE;            // 4608 words
constexpr int STAGE_F = A_F + B_ROWS * LDS_STRIDE;  // 11520 words
constexpr int SMEM_BYTES = 2 * STAGE_F * 4;         // 92160 B

__device__ __forceinline__ uint32_t f2tf32(float f) {
    uint32_t r;
    asm("cvt.rna.tf32.f32 %0, %1;" : "=r"(r) : "f"(f));
    return r;
}
__device__ __forceinline__ float tanh_ap(float x) {
    float y;
    asm("tanh.approx.f32 %0, %1;" : "=f"(y) : "f"(x));
    return y;
}
__device__ __forceinline__ float sig_ap(float x) {
    return fmaf(0.5f, tanh_ap(0.5f * x), 0.5f);
}
__device__ __forceinline__ void mma8(float* c, const uint32_t* a, const uint32_t* b) {
    asm volatile(
        "mma.sync.aligned.m16n8k8.row.col.f32.tf32.tf32.f32 "
        "{%0,%1,%2,%3}, {%4,%5,%6,%7}, {%8,%9}, {%0,%1,%2,%3};"
        : "+f"(c[0]), "+f"(c[1]), "+f"(c[2]), "+f"(c[3])
        : "r"(a[0]), "r"(a[1]), "r"(a[2]), "r"(a[3]), "r"(b[0]), "r"(b[1]));
}

}  // namespace

__global__ __launch_bounds__(256, 1)
void BlockDiagonalGRU_kernel(
    const float* __restrict__ x, const float* __restrict__ h,
    const float* __restrict__ Wih, const float* __restrict__ Whh,
    const float* __restrict__ bih, const float* __restrict__ bhh,
    float* __restrict__ out)
{
    extern __shared__ uint32_t sm[];

    const int tid  = threadIdx.x;
    const int wid  = tid >> 5;
    const int lane = tid & 31;
    const int gq   = lane >> 2;   // 0..7
    const int t4   = lane & 3;    // 0..3

    const int m  = blockIdx.x & 7;
    const int c  = (blockIdx.x >> 3) & 7;
    const int nb = blockIdx.x >> 6;

    const int wr = (wid >> 1) * 32;   // warp row base in 128-row tile
    const int wc = (wid & 1) * 32;    // warp col base in 64-col tile

    // ---- per-thread fill assignments (10 x 16B chunks per k-chunk) ----
    // ids 0..1023: A tile (row=id>>3, q=id&7); ids 1024..2559: W tiles.
    int aoff[4], soffA[4];
    #pragma unroll
    for (int ii = 0; ii < 4; ++ii) {
        const int id = tid + 256 * ii;
        const int row = id >> 3, q = id & 7;
        aoff[ii]  = row * HID + q * 4;           // + pass base + kc*32
        soffA[ii] = row * LDS_STRIDE + q * 4;
    }
    int woff[6], soffB[6];
    #pragma unroll
    for (int ii = 0; ii < 6; ++ii) {
        const int id = tid + 256 * (ii + 4) - 1024;
        const int wrow = id >> 3, q = id & 7;    // wrow = gate*64 + n_local
        const int gate = wrow >> 6, nl = wrow & 63;
        woff[ii]  = (gate * BS + c * 64 + nl) * BS + q * 4;
        soffB[ii] = A_F + wrow * LDS_STRIDE + q * 4;
    }

    const float* Abase[2] = { x + (size_t)(m * 128) * HID + nb * BS,
                              h + (size_t)(m * 128) * HID + nb * BS };
    const float* Wbase[2] = { Wih + (size_t)nb * G3 * BS,
                              Whh + (size_t)nb * G3 * BS };

    // ---- accumulators ----
    float accR[2][4][4] = {}, accZ[2][4][4] = {};
    float accI[2][4][4] = {}, accH[2][4][4] = {};

    float4 pf[10];

    auto load_pf = [&](int it) {
        const int p  = it >> 4;
        const int kc = it & 15;
        const float* Ab = Abase[p] + kc * TK;
        #pragma unroll
        for (int ii = 0; ii < 4; ++ii)
            pf[ii] = *reinterpret_cast<const float4*>(Ab + aoff[ii]);
        const float* Wb = Wbase[p] + kc * TK;
        #pragma unroll
        for (int ii = 0; ii < 6; ++ii)
            pf[ii + 4] = *reinterpret_cast<const float4*>(Wb + woff[ii]);
    };
    auto store_stage = [&](int st) {
        uint32_t* s = sm + st * STAGE_F;
        #pragma unroll
        for (int ii = 0; ii < 4; ++ii) {
            uint4 v = { f2tf32(pf[ii].x), f2tf32(pf[ii].y),
                        f2tf32(pf[ii].z), f2tf32(pf[ii].w) };
            *reinterpret_cast<uint4*>(s + soffA[ii]) = v;
        }
        #pragma unroll
        for (int ii = 0; ii < 6; ++ii) {
            uint4 v = { f2tf32(pf[ii + 4].x), f2tf32(pf[ii + 4].y),
                        f2tf32(pf[ii + 4].z), f2tf32(pf[ii + 4].w) };
            *reinterpret_cast<uint4*>(s + soffB[ii]) = v;
        }
    };

    // ---- prologue ----
    load_pf(0);
    store_stage(0);
    __syncthreads();

    // ---- mainloop: 32 k-chunks (pass0: x*Wih, pass1: h*Whh) ----
    for (int i = 0; i < 32; ++i) {
        if (i < 31) load_pf(i + 1);

        {
            const int p = i >> 4;
            const uint32_t* As = sm + (i & 1) * STAGE_F;
            const uint32_t* Bsm = As + A_F;
            float (*accN)[4][4] = p ? accH : accI;

            #pragma unroll
            for (int ks = 0; ks < 4; ++ks) {
                uint32_t a[2][4];
                #pragma unroll
                for (int mf = 0; mf < 2; ++mf) {
                    const int r0 = wr + mf * 16 + gq;
                    const int cb = ks * 8 + t4;
                    a[mf][0] = As[r0 * LDS_STRIDE + cb];
                    a[mf][1] = As[(r0 + 8) * LDS_STRIDE + cb];
                    a[mf][2] = As[r0 * LDS_STRIDE + cb + 4];
                    a[mf][3] = As[(r0 + 8) * LDS_STRIDE + cb + 4];
                }
                #pragma unroll
                for (int g3 = 0; g3 < 3; ++g3) {
                    #pragma unroll
                    for (int nf = 0; nf < 4; ++nf) {
                        const int nr = g3 * 64 + wc + nf * 8 + gq;
                        uint32_t b[2];
                        b[0] = Bsm[nr * LDS_STRIDE + ks * 8 + t4];
                        b[1] = Bsm[nr * LDS_STRIDE + ks * 8 + t4 + 4];
                        #pragma unroll
                        for (int mf = 0; mf < 2; ++mf) {
                            float* cc = (g3 == 0) ? accR[mf][nf]
                                      : (g3 == 1) ? accZ[mf][nf]
                                                  : accN[mf][nf];
                            mma8(cc, a[mf], b);
                        }
                    }
                }
            }
        }
        __syncthreads();
        if (i < 31) store_stage((i + 1) & 1);
        __syncthreads();
    }

    // ---- fused GRU epilogue ----
    const float* bi = bih + nb * G3;
    const float* bh = bhh + nb * G3;

    #pragma unroll
    for (int mf = 0; mf < 2; ++mf) {
        #pragma unroll
        for (int nf = 0; nf < 4; ++nf) {
            const int colb = c * 64 + wc + nf * 8 + 2 * t4;   // col in 512 block
            const int rowb = m * 128 + wr + mf * 16 + gq;
            #pragma unroll
            for (int half = 0; half < 2; ++half) {
                const int row = rowb + 8 * half;
                const int i0  = 2 * half;
                const size_t goff = (size_t)row * HID + nb * BS + colb;
                const float2 hv = *reinterpret_cast<const float2*>(h + goff);
                float res[2];
                #pragma unroll
                for (int k = 0; k < 2; ++k) {
                    const int cb = colb + k;
                    const float rp = accR[mf][nf][i0 + k] + __ldg(bi + cb) + __ldg(bh + cb);
                    const float zp = accZ[mf][nf][i0 + k] + __ldg(bi + BS + cb) + __ldg(bh + BS + cb);
                    const float ip = accI[mf][nf][i0 + k] + __ldg(bi + 2 * BS + cb);
                    const float hp = accH[mf][nf][i0 + k] + __ldg(bh + 2 * BS + cb);
                    const float r  = sig_ap(rp);
                    const float z  = sig_ap(zp);
                    const float ng = tanh_ap(fmaf(r, hp, ip));
                    const float hval = (k == 0) ? hv.x : hv.y;
                    res[k] = fmaf(z, hval - ng, ng);
                }
                *reinterpret_cast<float2*>(out + goff) = make_float2(res[0], res[1]);
            }
        }
    }
}

extern "C" void kernel_launch(void* const* d_in, const int* in_sizes, int n_in,
                              void* d_out, int out_size) {
    (void)in_sizes; (void)n_in; (void)out_size;
    cudaFuncSetAttribute(BlockDiagonalGRU_kernel,
                         cudaFuncAttributeMaxDynamicSharedMemorySize, SMEM_BYTES);
    BlockDiagonalGRU_kernel<<<512, 256, SMEM_BYTES>>>(
        (const float*)d_in[0], (const float*)d_in[1],
        (const float*)d_in[2], (const float*)d_in[3],
        (const float*)d_in[4], (const float*)d_in[5],
        (float*)d_out);
}